// round 13
// baseline (speedup 1.0000x reference)
#include <cuda_runtime.h>
#include <math.h>

// DifferentiableICP: B=32, N=M=2048, 5 soft-ICP iterations.
// R12 == R11 resubmitted (previous round died to a broker/container infra
// failure before measurement).
// R11: ex2.approx.f16x2 -> 2 exps per MUFU op. fp16 range made safe by the
//      shift y' = y - log2e*|st|^2 = -log2e*|st - t_m|^2 <= 0 (softmax is
//      shift-invariant; weights in (0,1], no max pass, no overflow/underflow
//      of the dominant terms). Per pair: MUFU 32->16 cyc; fma 24; cvt 12;
//      ~26 issue slots -> issue/fma-bound ~26 cyc/pair (-19%).
// Structure = R9: init + 5 iter (update folded into head) + final. 7 launches.

#define BB 32
#define NN 2048
#define MM 2048
#define ITERS 5
#define CHUNKS 32                    // CTAs per batch
#define ROWS_PER_CTA (NN / CHUNKS)   // 64
#define RPT 2                        // rows per thread
#define MSPLIT 4                     // warps per CTA == M segments
#define TPB (32 * MSPLIT)            // 128
#define NPAIR (MM / 2)               // 1024 packed target pairs
#define SEGPAIRS (NPAIR / MSPLIT)    // 256 pairs per segment

typedef unsigned long long ull;

// Scratch (allocation-free rule: __device__ globals)
__device__ ulonglong2 g_uv2[BB][NPAIR]; // packed ((2L2E*tx),(2L2E*ty)) pairs
__device__ ull        g_w2[BB][NPAIR];  // packed (-L2E*|t|^2) pairs
__device__ float      g_Tbuf[2][BB][4]; // (cos,sin,tx,ty), double-buffered
__device__ float      g_part[BB][CHUNKS][8];

// ---- packed f32x2 helpers (PTX-only; ptxas never auto-fuses FFMA2) --------
__device__ __forceinline__ ull fma2(ull a, ull b, ull c) {
    ull d; asm("fma.rn.f32x2 %0, %1, %2, %3;" : "=l"(d) : "l"(a), "l"(b), "l"(c));
    return d;
}
__device__ __forceinline__ ull add2(ull a, ull b) {
    ull d; asm("add.rn.f32x2 %0, %1, %2;" : "=l"(d) : "l"(a), "l"(b));
    return d;
}
__device__ __forceinline__ ull pack2(float lo, float hi) {
    ull d; asm("mov.b64 %0, {%1, %2};" : "=l"(d) : "f"(lo), "f"(hi));
    return d;
}
__device__ __forceinline__ void unpack2(ull v, float& lo, float& hi) {
    asm("mov.b64 {%0, %1}, %2;" : "=f"(lo), "=f"(hi) : "l"(v));
}

// Packed-pair weight: e = 2^(y + nssq) computed through f16x2 MUFU.
// y + nssq = -log2e * |st - t|^2 <= 0, so fp16 never overflows; dominant
// (near) weights are O(1) with ~2^-11 relative error; far weights underflow
// to 0 with negligible softmax mass. One ex2 op per TWO targets.
__device__ __forceinline__ ull expw2(ull y2, ull nssq2) {
    const ull yp = add2(y2, nssq2);
    float y0, y1; unpack2(yp, y0, y1);
    unsigned int h;                 // f16x2 {hi=y1, lo=y0}
    asm("cvt.rn.f16x2.f32 %0, %1, %2;" : "=r"(h) : "f"(y1), "f"(y0));
    asm("ex2.approx.f16x2 %0, %0;" : "+r"(h));
    float e0, e1;
    asm("{ .reg .b16 lo, hi;\n\t"
        "  mov.b32 {lo, hi}, %2;\n\t"
        "  cvt.f32.f16 %0, lo;\n\t"
        "  cvt.f32.f16 %1, hi; }"
        : "=f"(e0), "=f"(e1) : "r"(h));
    return pack2(e0, e1);
}

// ---------------------------------------------------------------------------
// Shared update math: given the 8 reduced sums p[] and T_old, produce T_new.
// R_delta = V @ U^T (SVD of H) == orthogonal polar factor of H^T, closed form.
// MUST be called with identical inputs everywhere it's used (bit-identical).
// ---------------------------------------------------------------------------
__device__ __forceinline__ void icp_compose(const float p[8],
                                            float cc, float ss, float ttx, float tty,
                                            float& c2, float& s2, float& tx2, float& ty2) {
    const float invN = 1.0f / (float)NN;
    const float csx = p[0] * invN, csy = p[1] * invN;
    const float ctx = p[2] * invN, cty = p[3] * invN;

    const float h00 = p[4] - p[0] * p[2] * invN;
    const float h01 = p[5] - p[0] * p[3] * invN;
    const float h10 = p[6] - p[1] * p[2] * invN;
    const float h11 = p[7] - p[1] * p[3] * invN;

    const float E  = 0.5f * (h00 + h11);
    const float F  = 0.5f * (h00 - h11);
    const float G  = 0.5f * (h01 + h10);
    const float Hh = 0.5f * (h01 - h10);
    const float det = h00 * h11 - h01 * h10;

    float r00, r01, r10, r11;
    if (det >= 0.0f) {           // rotation branch
        float iq = rsqrtf(E * E + Hh * Hh);
        r00 =  E * iq;  r01 = -Hh * iq;
        r10 = Hh * iq;  r11 =  E * iq;
    } else {                      // reflection branch
        float ir = rsqrtf(F * F + G * G);
        r00 =  F * ir;  r01 =  G * ir;
        r10 =  G * ir;  r11 = -F * ir;
    }

    const float ih = rsqrtf(r00 * r00 + r10 * r10);
    const float cD = r00 * ih;
    const float sD = r10 * ih;
    const float tDx = ctx - (r00 * csx + r01 * csy);
    const float tDy = cty - (r10 * csx + r11 * csy);

    c2  = cD * cc - sD * ss;
    s2  = sD * cc + cD * ss;
    tx2 = cD * ttx - sD * tty + tDx;
    ty2 = sD * ttx + cD * tty + tDy;
}

// ---------------------------------------------------------------------------
// Init: paired, log2e-folded target constants + initial transform (buf 0).
// ---------------------------------------------------------------------------
__global__ void icp_init_kernel(const float* __restrict__ target,
                                const float* __restrict__ init_t) {
    int g = blockIdx.x * blockDim.x + threadIdx.x;
    if (g < BB * NPAIR) {
        int b = g >> 10, p = g & (NPAIR - 1);
        float4 f = reinterpret_cast<const float4*>(target)[(size_t)b * NPAIR + p];
        const float L2E = 1.4426950408889634f;
        ulonglong2 uv;
        uv.x = pack2(2.0f * L2E * f.x, 2.0f * L2E * f.z);
        uv.y = pack2(2.0f * L2E * f.y, 2.0f * L2E * f.w);
        g_uv2[b][p] = uv;
        g_w2[b][p]  = pack2(-L2E * (f.x * f.x + f.y * f.y),
                            -L2E * (f.z * f.z + f.w * f.w));
    }
    if (g < BB) {
        float th = init_t[g * 3 + 0];
        g_Tbuf[0][g][0] = cosf(th);
        g_Tbuf[0][g][1] = sinf(th);
        g_Tbuf[0][g][2] = init_t[g * 3 + 1];
        g_Tbuf[0][g][3] = init_t[g * 3 + 2];
    }
}

// ---------------------------------------------------------------------------
// Iter kernel `it` (0..4). grid = BB*CHUNKS = 1024 CTAs, block = 128.
// Head (it>0): every CTA redundantly reduces previous g_part and composes
//   T_it from g_Tbuf[it&1]; chunk0 persists T_it to g_Tbuf[(it+1)&1].
// Body: f16x2-MUFU softmax mainloop writing this iteration's g_part.
// ---------------------------------------------------------------------------
__global__ void __launch_bounds__(TPB, 7)
icp_iter_kernel(const float* __restrict__ source, int it) {
    __shared__ ulonglong2 sUV[NPAIR];                     // 16 KB
    __shared__ ull        sW[NPAIR];                      // 8 KB
    __shared__ float4     sRow[MSPLIT - 1][ROWS_PER_CTA]; // 3 KB

    const int b     = blockIdx.x >> 5;
    const int chunk = blockIdx.x & 31;
    const int tid   = threadIdx.x;
    const int lane  = tid & 31;
    const int warp  = tid >> 5;          // == M-segment

    // Stage paired target constants (coalesced 16B/8B loads)
    for (int i = tid; i < NPAIR; i += TPB) {
        sUV[i] = g_uv2[b][i];
        sW[i]  = g_w2[b][i];
    }

    // ---- compute this iteration's transform (redundant per warp) ----
    const int rd = it & 1;
    float c, s, tx, ty;
    {
        const float cc  = g_Tbuf[rd][b][0];
        const float ss  = g_Tbuf[rd][b][1];
        const float ttx = g_Tbuf[rd][b][2];
        const float tty = g_Tbuf[rd][b][3];
        if (it == 0) {
            c = cc; s = ss; tx = ttx; ty = tty;
        } else {
            // lane == chunk index: reduce previous iteration's partials
            float p[8];
            #pragma unroll
            for (int k = 0; k < 8; ++k) p[k] = g_part[b][lane][k];
            #pragma unroll
            for (int off = 16; off; off >>= 1)
                #pragma unroll
                for (int k = 0; k < 8; ++k)
                    p[k] += __shfl_xor_sync(0xFFFFFFFFu, p[k], off);
            icp_compose(p, cc, ss, ttx, tty, c, s, tx, ty);
        }
        // persist T_it for the next kernel (double-buffered: no read/write race)
        if (chunk == 0 && tid == 0) {
            g_Tbuf[rd ^ 1][b][0] = c;
            g_Tbuf[rd ^ 1][b][1] = s;
            g_Tbuf[rd ^ 1][b][2] = tx;
            g_Tbuf[rd ^ 1][b][3] = ty;
        }
    }

    // st = R*source + t for this thread's 2 rows; per-row shift -L2E*|st|^2
    const float L2E = 1.4426950408889634f;
    float sx[RPT], sy[RPT];
    ull sx2[RPT], sy2[RPT], nssq2[RPT];
    #pragma unroll
    for (int k = 0; k < RPT; ++k) {
        const int row = chunk * ROWS_PER_CTA + lane + 32 * k;
        const float2 sv = reinterpret_cast<const float2*>(source)[(size_t)b * NN + row];
        sx[k] = c * sv.x - s * sv.y + tx;
        sy[k] = s * sv.x + c * sv.y + ty;
        sx2[k] = pack2(sx[k], sx[k]);
        sy2[k] = pack2(sy[k], sy[k]);
        const float nssq = -L2E * (sx[k] * sx[k] + sy[k] * sy[k]);
        nssq2[k] = pack2(nssq, nssq);
    }

    __syncthreads();

    // Single-pass softmax-weighted sums: 2 LDS/pair, f16x2 MUFU exp (1 op per
    // 2 targets). Weights are globally rescaled per row by e^{-|st|^2}; the
    // softmax ratio tcx/tcy is shift-invariant so downstream math is unchanged.
    ull se2[RPT], au2[RPT], av2[RPT];
    #pragma unroll
    for (int k = 0; k < RPT; ++k) { se2[k] = 0ull; au2[k] = 0ull; av2[k] = 0ull; }

    const int p0 = warp * SEGPAIRS;
    #pragma unroll 4
    for (int p = p0; p < p0 + SEGPAIRS; ++p) {
        const ulonglong2 uv = sUV[p];
        const ull u2 = uv.x;
        const ull v2 = uv.y;
        const ull w2 = sW[p];
        #pragma unroll
        for (int k = 0; k < RPT; ++k) {
            ull y2 = fma2(sx2[k], u2, w2);
            y2 = fma2(sy2[k], v2, y2);
            const ull e2 = expw2(y2, nssq2[k]);
            se2[k] = add2(se2[k], e2);
            au2[k] = fma2(e2, u2, au2[k]);
            av2[k] = fma2(e2, v2, av2[k]);
        }
    }

    // Horizontal add of the packed halves (fixed order: lo + hi)
    float se[RPT], au[RPT], av[RPT];
    #pragma unroll
    for (int k = 0; k < RPT; ++k) {
        float a0, a1;
        unpack2(se2[k], a0, a1); se[k] = a0 + a1;
        unpack2(au2[k], a0, a1); au[k] = a0 + a1;
        unpack2(av2[k], a0, a1); av[k] = a0 + a1;
    }

    // Publish segment partials (warps 1..3), combine in warp 0 (fixed order)
    if (warp > 0) {
        #pragma unroll
        for (int k = 0; k < RPT; ++k)
            sRow[warp - 1][lane + 32 * k] = make_float4(se[k], au[k], av[k], 0.0f);
    }
    __syncthreads();

    if (warp == 0) {
        float p[8];
        #pragma unroll
        for (int i = 0; i < 8; ++i) p[i] = 0.0f;

        #pragma unroll
        for (int k = 0; k < RPT; ++k) {
            float sek = se[k], auk = au[k], avk = av[k];
            #pragma unroll
            for (int q = 0; q < MSPLIT - 1; ++q) {   // fixed order seg1..3
                const float4 f = sRow[q][lane + 32 * k];
                sek += f.x; auk += f.y; avk += f.z;
            }
            const float KINV = 0.34657359027997264f; // ln(2)/2 (undo folded 2*log2e)
            const float inv = KINV / sek;
            const float tcx = auk * inv;
            const float tcy = avk * inv;
            // fixed-order accumulation over k
            p[0] += sx[k];        p[1] += sy[k];
            p[2] += tcx;          p[3] += tcy;
            p[4] += sx[k] * tcx;  p[5] += sx[k] * tcy;
            p[6] += sy[k] * tcx;  p[7] += sy[k] * tcy;
        }

        // Deterministic warp butterfly
        #pragma unroll
        for (int off = 16; off; off >>= 1)
            #pragma unroll
            for (int i = 0; i < 8; ++i)
                p[i] += __shfl_xor_sync(0xFFFFFFFFu, p[i], off);

        if (lane == 0) {
            #pragma unroll
            for (int i = 0; i < 8; ++i) g_part[b][chunk][i] = p[i];
        }
    }
}

// ---------------------------------------------------------------------------
// Final kernel: reduce last iteration's partials, compose T_5, write output.
// grid = BB x 32 threads. Reads T_4 from g_Tbuf[ITERS & 1] == g_Tbuf[1].
// ---------------------------------------------------------------------------
__global__ void icp_final_kernel(float* __restrict__ out) {
    const int b = blockIdx.x;
    const int t = threadIdx.x;

    float p[8];
    #pragma unroll
    for (int k = 0; k < 8; ++k) p[k] = g_part[b][t][k];
    #pragma unroll
    for (int off = 16; off; off >>= 1)
        #pragma unroll
        for (int k = 0; k < 8; ++k)
            p[k] += __shfl_xor_sync(0xFFFFFFFFu, p[k], off);

    if (t == 0) {
        const int rd = ITERS & 1;   // buffer holding T_{ITERS-1}
        float c2, s2, tx2, ty2;
        icp_compose(p, g_Tbuf[rd][b][0], g_Tbuf[rd][b][1],
                       g_Tbuf[rd][b][2], g_Tbuf[rd][b][3],
                    c2, s2, tx2, ty2);
        out[b * 3 + 0] = atan2f(s2, c2);
        out[b * 3 + 1] = tx2;
        out[b * 3 + 2] = ty2;
    }
}

// ---------------------------------------------------------------------------
extern "C" void kernel_launch(void* const* d_in, const int* in_sizes, int n_in,
                              void* d_out, int out_size) {
    const float* source = (const float*)d_in[0];   // (32, 2048, 2)
    const float* target = (const float*)d_in[1];   // (32, 2048, 2)
    const float* init_t = (const float*)d_in[2];   // (32, 3)
    float* out = (float*)d_out;                    // (32, 3)

    icp_init_kernel<<<(BB * NPAIR + 255) / 256, 256>>>(target, init_t);
    for (int it = 0; it < ITERS; ++it)
        icp_iter_kernel<<<BB * CHUNKS, TPB>>>(source, it);
    icp_final_kernel<<<BB, 32>>>(out);
}

// round 15
// speedup vs baseline: 1.1977x; 1.1977x over previous
#include <cuda_runtime.h>
#include <cuda_fp16.h>
#include <math.h>

// DifferentiableICP: B=32, N=M=2048, 5 soft-ICP iterations.
// R15: surgical precision mix, from the measured error decomposition:
//   - logits in f32 (R9 dot form + row shift)  -> no coord quantization
//   - exp via cvt.rn.f16x2.f32 + ex2.approx.f16x2 (2 exps/MUFU; 4.5e-6 proven)
//   - accumulate se/au/av in f16x2, FLUSH to f32 every 16 pairs
//     (f16 chain error ~2^-12*L: L=256 -> 6e-3 (R14 fail); L=16 -> 4e-4/row)
//   - au/av accumulate e * f16(target) directly -> tc = au/se, no unscale
// XU ledger/pair: 2 ex2(16) + 2 cvt-in(8) + 0.75 flush-cvt(3) = 27 cyc binding
// vs R9's 32-cyc MUFU wall (-16%). smem 32KB: sRow unioned over dead sUV.
// Structure = R9: init + 5 iter (update folded into head) + final. 7 launches.

#define BB 32
#define NN 2048
#define MM 2048
#define ITERS 5
#define CHUNKS 32                    // CTAs per batch
#define ROWS_PER_CTA (NN / CHUNKS)   // 64
#define RPT 2                        // rows per thread
#define MSPLIT 4                     // warps per CTA == M segments
#define TPB (32 * MSPLIT)            // 128
#define NPAIR (MM / 2)               // 1024 packed target pairs
#define SEGPAIRS (NPAIR / MSPLIT)    // 256 pairs per segment
#define FLUSH 16                     // f16-accumulate block length (pairs)

typedef unsigned long long ull;

// Scratch (allocation-free rule: __device__ globals)
__device__ ulonglong2 g_uv2[BB][NPAIR]; // packed ((2L2E*tx),(2L2E*ty)) f32 pairs
__device__ ull        g_w2[BB][NPAIR];  // packed (-L2E*|t|^2) f32 pairs
__device__ uint2      g_th[BB][NPAIR];  // (txh2, tyh2): f16x2 raw target pairs
__device__ float      g_Tbuf[2][BB][4]; // (cos,sin,tx,ty), double-buffered
__device__ float      g_part[BB][CHUNKS][8];

// ---- packed f32x2 helpers (PTX-only; ptxas never auto-fuses FFMA2) --------
__device__ __forceinline__ ull fma2(ull a, ull b, ull c) {
    ull d; asm("fma.rn.f32x2 %0, %1, %2, %3;" : "=l"(d) : "l"(a), "l"(b), "l"(c));
    return d;
}
__device__ __forceinline__ ull add2(ull a, ull b) {
    ull d; asm("add.rn.f32x2 %0, %1, %2;" : "=l"(d) : "l"(a), "l"(b));
    return d;
}
__device__ __forceinline__ ull pack2(float lo, float hi) {
    ull d; asm("mov.b64 %0, {%1, %2};" : "=l"(d) : "f"(lo), "f"(hi));
    return d;
}
__device__ __forceinline__ void unpack2(ull v, float& lo, float& hi) {
    asm("mov.b64 {%0, %1}, %2;" : "=f"(lo), "=f"(hi) : "l"(v));
}
__device__ __forceinline__ unsigned int h2bits(__half2 h) {
    return *reinterpret_cast<unsigned int*>(&h);
}
__device__ __forceinline__ __half2 bits2h(unsigned int u) {
    return *reinterpret_cast<__half2*>(&u);
}

// f32x2 logit pair -> f16x2 weights: one packing cvt + one f16x2 MUFU exp.
__device__ __forceinline__ __half2 expw2(ull y2) {
    float y0, y1; unpack2(y2, y0, y1);
    unsigned int h;                 // f16x2 {lo=y0, hi=y1}
    asm("cvt.rn.f16x2.f32 %0, %1, %2;" : "=r"(h) : "f"(y1), "f"(y0));
    asm("ex2.approx.f16x2 %0, %0;" : "+r"(h));
    return bits2h(h);
}

// ---------------------------------------------------------------------------
// Shared update math: given the 8 reduced sums p[] and T_old, produce T_new.
// R_delta = V @ U^T (SVD of H) == orthogonal polar factor of H^T, closed form.
// MUST be called with identical inputs everywhere it's used (bit-identical).
// ---------------------------------------------------------------------------
__device__ __forceinline__ void icp_compose(const float p[8],
                                            float cc, float ss, float ttx, float tty,
                                            float& c2, float& s2, float& tx2, float& ty2) {
    const float invN = 1.0f / (float)NN;
    const float csx = p[0] * invN, csy = p[1] * invN;
    const float ctx = p[2] * invN, cty = p[3] * invN;

    const float h00 = p[4] - p[0] * p[2] * invN;
    const float h01 = p[5] - p[0] * p[3] * invN;
    const float h10 = p[6] - p[1] * p[2] * invN;
    const float h11 = p[7] - p[1] * p[3] * invN;

    const float E  = 0.5f * (h00 + h11);
    const float F  = 0.5f * (h00 - h11);
    const float G  = 0.5f * (h01 + h10);
    const float Hh = 0.5f * (h01 - h10);
    const float det = h00 * h11 - h01 * h10;

    float r00, r01, r10, r11;
    if (det >= 0.0f) {           // rotation branch
        float iq = rsqrtf(E * E + Hh * Hh);
        r00 =  E * iq;  r01 = -Hh * iq;
        r10 = Hh * iq;  r11 =  E * iq;
    } else {                      // reflection branch
        float ir = rsqrtf(F * F + G * G);
        r00 =  F * ir;  r01 =  G * ir;
        r10 =  G * ir;  r11 = -F * ir;
    }

    const float ih = rsqrtf(r00 * r00 + r10 * r10);
    const float cD = r00 * ih;
    const float sD = r10 * ih;
    const float tDx = ctx - (r00 * csx + r01 * csy);
    const float tDy = cty - (r10 * csx + r11 * csy);

    c2  = cD * cc - sD * ss;
    s2  = sD * cc + cD * ss;
    tx2 = cD * ttx - sD * tty + tDx;
    ty2 = sD * ttx + cD * tty + tDy;
}

// ---------------------------------------------------------------------------
// Init: f32 log2e-folded pairs + f16 raw target pairs + initial transform.
// ---------------------------------------------------------------------------
__global__ void icp_init_kernel(const float* __restrict__ target,
                                const float* __restrict__ init_t) {
    int g = blockIdx.x * blockDim.x + threadIdx.x;
    if (g < BB * NPAIR) {
        int b = g >> 10, p = g & (NPAIR - 1);
        float4 f = reinterpret_cast<const float4*>(target)[(size_t)b * NPAIR + p];
        const float L2E = 1.4426950408889634f;
        ulonglong2 uv;
        uv.x = pack2(2.0f * L2E * f.x, 2.0f * L2E * f.z);
        uv.y = pack2(2.0f * L2E * f.y, 2.0f * L2E * f.w);
        g_uv2[b][p] = uv;
        g_w2[b][p]  = pack2(-L2E * (f.x * f.x + f.y * f.y),
                            -L2E * (f.z * f.z + f.w * f.w));
        uint2 th;
        th.x = h2bits(__floats2half2_rn(f.x, f.z));   // lo = target 2p
        th.y = h2bits(__floats2half2_rn(f.y, f.w));
        g_th[b][p] = th;
    }
    if (g < BB) {
        float th = init_t[g * 3 + 0];
        g_Tbuf[0][g][0] = cosf(th);
        g_Tbuf[0][g][1] = sinf(th);
        g_Tbuf[0][g][2] = init_t[g * 3 + 1];
        g_Tbuf[0][g][3] = init_t[g * 3 + 2];
    }
}

// ---------------------------------------------------------------------------
// Iter kernel `it` (0..4). grid = BB*CHUNKS = 1024 CTAs, block = 128.
// Head (it>0): every CTA redundantly reduces previous g_part and composes
//   T_it from g_Tbuf[it&1]; chunk0 persists T_it to g_Tbuf[(it+1)&1].
// Body: f32-logit / f16-exp / block-flushed-f16-accumulate mainloop.
// ---------------------------------------------------------------------------
__global__ void __launch_bounds__(TPB, 7)
icp_iter_kernel(const float* __restrict__ source, int it) {
    // 32 KB unioned smem: sUV[16K) | sW[8K) | sTH[8K). sRow (3KB) aliases the
    // start of sUV, which is dead after the mainloop (guarded by syncthreads).
    __shared__ __align__(16) char smem_raw[32 * 1024];
    ulonglong2* sUV = reinterpret_cast<ulonglong2*>(smem_raw);
    ull*        sW  = reinterpret_cast<ull*>(smem_raw + 16 * 1024);
    uint2*      sTH = reinterpret_cast<uint2*>(smem_raw + 24 * 1024);
    float4 (*sRow)[ROWS_PER_CTA] =
        reinterpret_cast<float4 (*)[ROWS_PER_CTA]>(smem_raw);

    const int b     = blockIdx.x >> 5;
    const int chunk = blockIdx.x & 31;
    const int tid   = threadIdx.x;
    const int lane  = tid & 31;
    const int warp  = tid >> 5;          // == M-segment

    // Stage target constants (coalesced 16B/8B/8B loads)
    for (int i = tid; i < NPAIR; i += TPB) {
        sUV[i] = g_uv2[b][i];
        sW[i]  = g_w2[b][i];
        sTH[i] = g_th[b][i];
    }

    // ---- compute this iteration's transform (redundant per warp) ----
    const int rd = it & 1;
    float c, s, tx, ty;
    {
        const float cc  = g_Tbuf[rd][b][0];
        const float ss  = g_Tbuf[rd][b][1];
        const float ttx = g_Tbuf[rd][b][2];
        const float tty = g_Tbuf[rd][b][3];
        if (it == 0) {
            c = cc; s = ss; tx = ttx; ty = tty;
        } else {
            // lane == chunk index: reduce previous iteration's partials
            float p[8];
            #pragma unroll
            for (int k = 0; k < 8; ++k) p[k] = g_part[b][lane][k];
            #pragma unroll
            for (int off = 16; off; off >>= 1)
                #pragma unroll
                for (int k = 0; k < 8; ++k)
                    p[k] += __shfl_xor_sync(0xFFFFFFFFu, p[k], off);
            icp_compose(p, cc, ss, ttx, tty, c, s, tx, ty);
        }
        // persist T_it for the next kernel (double-buffered: no read/write race)
        if (chunk == 0 && tid == 0) {
            g_Tbuf[rd ^ 1][b][0] = c;
            g_Tbuf[rd ^ 1][b][1] = s;
            g_Tbuf[rd ^ 1][b][2] = tx;
            g_Tbuf[rd ^ 1][b][3] = ty;
        }
    }

    // st = R*source + t for this thread's 2 rows; per-row shift -L2E*|st|^2
    const float L2E = 1.4426950408889634f;
    float sx[RPT], sy[RPT];
    ull sx2[RPT], sy2[RPT], nssq2[RPT];
    #pragma unroll
    for (int k = 0; k < RPT; ++k) {
        const int row = chunk * ROWS_PER_CTA + lane + 32 * k;
        const float2 sv = reinterpret_cast<const float2*>(source)[(size_t)b * NN + row];
        sx[k] = c * sv.x - s * sv.y + tx;
        sy[k] = s * sv.x + c * sv.y + ty;
        sx2[k] = pack2(sx[k], sx[k]);
        sy2[k] = pack2(sy[k], sy[k]);
        const float nssq = -L2E * (sx[k] * sx[k] + sy[k] * sy[k]);
        nssq2[k] = pack2(nssq, nssq);
    }

    __syncthreads();

    // Mainloop: f32 logit -> f16x2 exp -> f16 accumulate, f32 flush per block.
    float sef[RPT], auf[RPT], avf[RPT];
    #pragma unroll
    for (int k = 0; k < RPT; ++k) { sef[k] = 0.0f; auf[k] = 0.0f; avf[k] = 0.0f; }

    const int p0 = warp * SEGPAIRS;
    for (int blk = 0; blk < SEGPAIRS / FLUSH; ++blk) {
        __half2 seh[RPT], auh[RPT], avh[RPT];
        #pragma unroll
        for (int k = 0; k < RPT; ++k) {
            seh[k] = __floats2half2_rn(0.0f, 0.0f);
            auh[k] = seh[k];
            avh[k] = seh[k];
        }

        const int pb = p0 + blk * FLUSH;
        #pragma unroll 4
        for (int j = 0; j < FLUSH; ++j) {
            const int p = pb + j;
            const ulonglong2 uv = sUV[p];
            const ull w2 = sW[p];
            const uint2 th = sTH[p];
            const __half2 txh = bits2h(th.x);
            const __half2 tyh = bits2h(th.y);
            #pragma unroll
            for (int k = 0; k < RPT; ++k) {
                ull y2 = fma2(sx2[k], uv.x, w2);
                y2 = fma2(sy2[k], uv.y, y2);
                y2 = add2(y2, nssq2[k]);          // shifted logit <= 0
                const __half2 e = expw2(y2);      // 1 cvt + 1 MUFU for 2 targets
                seh[k] = __hadd2(seh[k], e);
                auh[k] = __hfma2(e, txh, auh[k]);
                avh[k] = __hfma2(e, tyh, avh[k]);
            }
        }

        // Flush block sums to f32 (fixed order: lo + hi, then running add)
        #pragma unroll
        for (int k = 0; k < RPT; ++k) {
            const float2 a = __half22float2(seh[k]);
            const float2 u = __half22float2(auh[k]);
            const float2 v = __half22float2(avh[k]);
            sef[k] += a.x + a.y;
            auf[k] += u.x + u.y;
            avf[k] += v.x + v.y;
        }
    }

    __syncthreads();   // all warps done reading sUV before sRow aliases it

    // Publish segment partials (warps 1..3), combine in warp 0 (fixed order)
    if (warp > 0) {
        #pragma unroll
        for (int k = 0; k < RPT; ++k)
            sRow[warp - 1][lane + 32 * k] = make_float4(sef[k], auf[k], avf[k], 0.0f);
    }
    __syncthreads();

    if (warp == 0) {
        float p[8];
        #pragma unroll
        for (int i = 0; i < 8; ++i) p[i] = 0.0f;

        #pragma unroll
        for (int k = 0; k < RPT; ++k) {
            float sek = sef[k], auk = auf[k], avk = avf[k];
            #pragma unroll
            for (int q = 0; q < MSPLIT - 1; ++q) {   // fixed order seg1..3
                const float4 f = sRow[q][lane + 32 * k];
                sek += f.x; auk += f.y; avk += f.z;
            }
            // au/av accumulated against RAW f16 targets -> direct ratio
            const float inv = 1.0f / sek;
            const float tcx = auk * inv;
            const float tcy = avk * inv;
            // fixed-order accumulation over k
            p[0] += sx[k];        p[1] += sy[k];
            p[2] += tcx;          p[3] += tcy;
            p[4] += sx[k] * tcx;  p[5] += sx[k] * tcy;
            p[6] += sy[k] * tcx;  p[7] += sy[k] * tcy;
        }

        // Deterministic warp butterfly
        #pragma unroll
        for (int off = 16; off; off >>= 1)
            #pragma unroll
            for (int i = 0; i < 8; ++i)
                p[i] += __shfl_xor_sync(0xFFFFFFFFu, p[i], off);

        if (lane == 0) {
            #pragma unroll
            for (int i = 0; i < 8; ++i) g_part[b][chunk][i] = p[i];
        }
    }
}

// ---------------------------------------------------------------------------
// Final kernel: reduce last iteration's partials, compose T_5, write output.
// grid = BB x 32 threads. Reads T_4 from g_Tbuf[ITERS & 1] == g_Tbuf[1].
// ---------------------------------------------------------------------------
__global__ void icp_final_kernel(float* __restrict__ out) {
    const int b = blockIdx.x;
    const int t = threadIdx.x;

    float p[8];
    #pragma unroll
    for (int k = 0; k < 8; ++k) p[k] = g_part[b][t][k];
    #pragma unroll
    for (int off = 16; off; off >>= 1)
        #pragma unroll
        for (int k = 0; k < 8; ++k)
            p[k] += __shfl_xor_sync(0xFFFFFFFFu, p[k], off);

    if (t == 0) {
        const int rd = ITERS & 1;   // buffer holding T_{ITERS-1}
        float c2, s2, tx2, ty2;
        icp_compose(p, g_Tbuf[rd][b][0], g_Tbuf[rd][b][1],
                       g_Tbuf[rd][b][2], g_Tbuf[rd][b][3],
                    c2, s2, tx2, ty2);
        out[b * 3 + 0] = atan2f(s2, c2);
        out[b * 3 + 1] = tx2;
        out[b * 3 + 2] = ty2;
    }
}

// ---------------------------------------------------------------------------
extern "C" void kernel_launch(void* const* d_in, const int* in_sizes, int n_in,
                              void* d_out, int out_size) {
    const float* source = (const float*)d_in[0];   // (32, 2048, 2)
    const float* target = (const float*)d_in[1];   // (32, 2048, 2)
    const float* init_t = (const float*)d_in[2];   // (32, 3)
    float* out = (float*)d_out;                    // (32, 3)

    icp_init_kernel<<<(BB * NPAIR + 255) / 256, 256>>>(target, init_t);
    for (int it = 0; it < ITERS; ++it)
        icp_iter_kernel<<<BB * CHUNKS, TPB>>>(source, it);
    icp_final_kernel<<<BB, 32>>>(out);
}

// round 16
// speedup vs baseline: 1.2622x; 1.0539x over previous
#include <cuda_runtime.h>
#include <math.h>

// DifferentiableICP: B=32, N=M=2048, 5 soft-ICP iterations.
// R16: consolidate on the R9 mainloop (best measured: 31.5us/iter vs 29.9us
//      MUFU floor; all f16-exp variants slower) and delete the init kernel:
//      - iter CTAs compute (u,v,w) from RAW target during smem staging
//        (1 LDG.128 + ~6 flops/pair, overlapped with head compute)
//      - T0 computed redundantly per-CTA from init_t (cos/sin; identical SASS
//        + identical input -> bit-identical across CTAs)
//      7 launches -> 6; 6MB constant scratch gone.
// Mainloop (unchanged from R9): f32x2 FMA dot-form logit, ex2.approx.ftz.f32,
// 2 LDS/pair, MUFU-paced at 32 cyc/pair/warp.

#define BB 32
#define NN 2048
#define MM 2048
#define ITERS 5
#define CHUNKS 32                    // CTAs per batch
#define ROWS_PER_CTA (NN / CHUNKS)   // 64
#define RPT 2                        // rows per thread
#define MSPLIT 4                     // warps per CTA == M segments
#define TPB (32 * MSPLIT)            // 128
#define NPAIR (MM / 2)               // 1024 packed target pairs
#define SEGPAIRS (NPAIR / MSPLIT)    // 256 pairs per segment

typedef unsigned long long ull;

// Scratch (allocation-free rule: __device__ globals)
__device__ float g_Tbuf[2][BB][4];   // (cos,sin,tx,ty), double-buffered
__device__ float g_part[BB][CHUNKS][8];

// ---- packed f32x2 helpers (PTX-only; ptxas never auto-fuses FFMA2) --------
__device__ __forceinline__ ull fma2(ull a, ull b, ull c) {
    ull d; asm("fma.rn.f32x2 %0, %1, %2, %3;" : "=l"(d) : "l"(a), "l"(b), "l"(c));
    return d;
}
__device__ __forceinline__ ull add2(ull a, ull b) {
    ull d; asm("add.rn.f32x2 %0, %1, %2;" : "=l"(d) : "l"(a), "l"(b));
    return d;
}
__device__ __forceinline__ ull pack2(float lo, float hi) {
    ull d; asm("mov.b64 %0, {%1, %2};" : "=l"(d) : "f"(lo), "f"(hi));
    return d;
}
__device__ __forceinline__ void unpack2(ull v, float& lo, float& hi) {
    asm("mov.b64 {%0, %1}, %2;" : "=f"(lo), "=f"(hi) : "l"(v));
}
__device__ __forceinline__ float ex2f(float x) {
    float e; asm("ex2.approx.ftz.f32 %0, %1;" : "=f"(e) : "f"(x));
    return e;
}

// ---------------------------------------------------------------------------
// Shared update math: given the 8 reduced sums p[] and T_old, produce T_new.
// R_delta = V @ U^T (SVD of H) == orthogonal polar factor of H^T, closed form.
// MUST be called with identical inputs everywhere it's used (bit-identical).
// ---------------------------------------------------------------------------
__device__ __forceinline__ void icp_compose(const float p[8],
                                            float cc, float ss, float ttx, float tty,
                                            float& c2, float& s2, float& tx2, float& ty2) {
    const float invN = 1.0f / (float)NN;
    const float csx = p[0] * invN, csy = p[1] * invN;
    const float ctx = p[2] * invN, cty = p[3] * invN;

    const float h00 = p[4] - p[0] * p[2] * invN;
    const float h01 = p[5] - p[0] * p[3] * invN;
    const float h10 = p[6] - p[1] * p[2] * invN;
    const float h11 = p[7] - p[1] * p[3] * invN;

    const float E  = 0.5f * (h00 + h11);
    const float F  = 0.5f * (h00 - h11);
    const float G  = 0.5f * (h01 + h10);
    const float Hh = 0.5f * (h01 - h10);
    const float det = h00 * h11 - h01 * h10;

    float r00, r01, r10, r11;
    if (det >= 0.0f) {           // rotation branch
        float iq = rsqrtf(E * E + Hh * Hh);
        r00 =  E * iq;  r01 = -Hh * iq;
        r10 = Hh * iq;  r11 =  E * iq;
    } else {                      // reflection branch
        float ir = rsqrtf(F * F + G * G);
        r00 =  F * ir;  r01 =  G * ir;
        r10 =  G * ir;  r11 = -F * ir;
    }

    const float ih = rsqrtf(r00 * r00 + r10 * r10);
    const float cD = r00 * ih;
    const float sD = r10 * ih;
    const float tDx = ctx - (r00 * csx + r01 * csy);
    const float tDy = cty - (r10 * csx + r11 * csy);

    c2  = cD * cc - sD * ss;
    s2  = sD * cc + cD * ss;
    tx2 = cD * ttx - sD * tty + tDx;
    ty2 = sD * ttx + cD * tty + tDy;
}

// ---------------------------------------------------------------------------
// Iter kernel `it` (0..4). grid = BB*CHUNKS = 1024 CTAs, block = 128.
// Staging: compute (u,v,w) from RAW target into smem (no init kernel).
// Head (it==0): T0 from init_t directly (redundant per CTA, bit-identical).
// Head (it>0): every CTA redundantly reduces previous g_part and composes
//   T_it from g_Tbuf[it&1]; chunk0 persists T_it to g_Tbuf[(it+1)&1].
// Body: MUFU-paced f32 softmax mainloop writing this iteration's g_part.
// ---------------------------------------------------------------------------
__global__ void __launch_bounds__(TPB, 8)
icp_iter_kernel(const float* __restrict__ source,
                const float* __restrict__ target,
                const float* __restrict__ init_t, int it) {
    __shared__ ulonglong2 sUV[NPAIR];                     // 16 KB
    __shared__ ull        sW[NPAIR];                      // 8 KB
    __shared__ float4     sRow[MSPLIT - 1][ROWS_PER_CTA]; // 3 KB

    const int b     = blockIdx.x >> 5;
    const int chunk = blockIdx.x & 31;
    const int tid   = threadIdx.x;
    const int lane  = tid & 31;
    const int warp  = tid >> 5;          // == M-segment

    const float L2E = 1.4426950408889634f;

    // Stage constants computed from raw target (coalesced 16B loads)
    for (int i = tid; i < NPAIR; i += TPB) {
        const float4 f = reinterpret_cast<const float4*>(target)[(size_t)b * NPAIR + i];
        ulonglong2 uv;
        uv.x = pack2(2.0f * L2E * f.x, 2.0f * L2E * f.z);
        uv.y = pack2(2.0f * L2E * f.y, 2.0f * L2E * f.w);
        sUV[i] = uv;
        sW[i]  = pack2(-L2E * (f.x * f.x + f.y * f.y),
                       -L2E * (f.z * f.z + f.w * f.w));
    }

    // ---- compute this iteration's transform (redundant per CTA/warp) ----
    const int rd = it & 1;
    float c, s, tx, ty;
    {
        if (it == 0) {
            const float th = init_t[b * 3 + 0];
            c  = cosf(th);
            s  = sinf(th);
            tx = init_t[b * 3 + 1];
            ty = init_t[b * 3 + 2];
        } else {
            const float cc  = g_Tbuf[rd][b][0];
            const float ss  = g_Tbuf[rd][b][1];
            const float ttx = g_Tbuf[rd][b][2];
            const float tty = g_Tbuf[rd][b][3];
            // lane == chunk index: reduce previous iteration's partials
            float p[8];
            #pragma unroll
            for (int k = 0; k < 8; ++k) p[k] = g_part[b][lane][k];
            #pragma unroll
            for (int off = 16; off; off >>= 1)
                #pragma unroll
                for (int k = 0; k < 8; ++k)
                    p[k] += __shfl_xor_sync(0xFFFFFFFFu, p[k], off);
            icp_compose(p, cc, ss, ttx, tty, c, s, tx, ty);
        }
        // persist T_it for the next kernel (double-buffered: no read/write race)
        if (chunk == 0 && tid == 0) {
            g_Tbuf[rd ^ 1][b][0] = c;
            g_Tbuf[rd ^ 1][b][1] = s;
            g_Tbuf[rd ^ 1][b][2] = tx;
            g_Tbuf[rd ^ 1][b][3] = ty;
        }
    }

    // st = R*source + t for this thread's 2 rows
    float sx[RPT], sy[RPT];
    ull sx2[RPT], sy2[RPT];
    #pragma unroll
    for (int k = 0; k < RPT; ++k) {
        const int row = chunk * ROWS_PER_CTA + lane + 32 * k;
        const float2 sv = reinterpret_cast<const float2*>(source)[(size_t)b * NN + row];
        sx[k] = c * sv.x - s * sv.y + tx;
        sy[k] = s * sv.x + c * sv.y + ty;
        sx2[k] = pack2(sx[k], sx[k]);
        sy2[k] = pack2(sy[k], sy[k]);
    }

    __syncthreads();

    // Packed single-pass softmax-weighted sums: 2 LDS/pair, reused x2 rows.
    ull se2[RPT], au2[RPT], av2[RPT];
    #pragma unroll
    for (int k = 0; k < RPT; ++k) { se2[k] = 0ull; au2[k] = 0ull; av2[k] = 0ull; }

    const int p0 = warp * SEGPAIRS;
    #pragma unroll 4
    for (int p = p0; p < p0 + SEGPAIRS; ++p) {
        const ulonglong2 uv = sUV[p];
        const ull u2 = uv.x;
        const ull v2 = uv.y;
        const ull w2 = sW[p];
        #pragma unroll
        for (int k = 0; k < RPT; ++k) {
            ull y2 = fma2(sx2[k], u2, w2);
            y2 = fma2(sy2[k], v2, y2);
            float y0, y1; unpack2(y2, y0, y1);
            const ull e2 = pack2(ex2f(y0), ex2f(y1));
            se2[k] = add2(se2[k], e2);
            au2[k] = fma2(e2, u2, au2[k]);
            av2[k] = fma2(e2, v2, av2[k]);
        }
    }

    // Horizontal add of the packed halves (fixed order: lo + hi)
    float se[RPT], au[RPT], av[RPT];
    #pragma unroll
    for (int k = 0; k < RPT; ++k) {
        float a0, a1;
        unpack2(se2[k], a0, a1); se[k] = a0 + a1;
        unpack2(au2[k], a0, a1); au[k] = a0 + a1;
        unpack2(av2[k], a0, a1); av[k] = a0 + a1;
    }

    // Publish segment partials (warps 1..3), combine in warp 0 (fixed order)
    if (warp > 0) {
        #pragma unroll
        for (int k = 0; k < RPT; ++k)
            sRow[warp - 1][lane + 32 * k] = make_float4(se[k], au[k], av[k], 0.0f);
    }
    __syncthreads();

    if (warp == 0) {
        float p[8];
        #pragma unroll
        for (int i = 0; i < 8; ++i) p[i] = 0.0f;

        #pragma unroll
        for (int k = 0; k < RPT; ++k) {
            float sek = se[k], auk = au[k], avk = av[k];
            #pragma unroll
            for (int q = 0; q < MSPLIT - 1; ++q) {   // fixed order seg1..3
                const float4 f = sRow[q][lane + 32 * k];
                sek += f.x; auk += f.y; avk += f.z;
            }
            const float KINV = 0.34657359027997264f; // ln(2)/2 (undo folded 2*log2e)
            const float inv = KINV / sek;
            const float tcx = auk * inv;
            const float tcy = avk * inv;
            // fixed-order accumulation over k
            p[0] += sx[k];        p[1] += sy[k];
            p[2] += tcx;          p[3] += tcy;
            p[4] += sx[k] * tcx;  p[5] += sx[k] * tcy;
            p[6] += sy[k] * tcx;  p[7] += sy[k] * tcy;
        }

        // Deterministic warp butterfly
        #pragma unroll
        for (int off = 16; off; off >>= 1)
            #pragma unroll
            for (int i = 0; i < 8; ++i)
                p[i] += __shfl_xor_sync(0xFFFFFFFFu, p[i], off);

        if (lane == 0) {
            #pragma unroll
            for (int i = 0; i < 8; ++i) g_part[b][chunk][i] = p[i];
        }
    }
}

// ---------------------------------------------------------------------------
// Final kernel: reduce last iteration's partials, compose T_5, write output.
// grid = BB x 32 threads. Reads T_4 from g_Tbuf[ITERS & 1] == g_Tbuf[1].
// ---------------------------------------------------------------------------
__global__ void icp_final_kernel(float* __restrict__ out) {
    const int b = blockIdx.x;
    const int t = threadIdx.x;

    float p[8];
    #pragma unroll
    for (int k = 0; k < 8; ++k) p[k] = g_part[b][t][k];
    #pragma unroll
    for (int off = 16; off; off >>= 1)
        #pragma unroll
        for (int k = 0; k < 8; ++k)
            p[k] += __shfl_xor_sync(0xFFFFFFFFu, p[k], off);

    if (t == 0) {
        const int rd = ITERS & 1;   // buffer holding T_{ITERS-1}
        float c2, s2, tx2, ty2;
        icp_compose(p, g_Tbuf[rd][b][0], g_Tbuf[rd][b][1],
                       g_Tbuf[rd][b][2], g_Tbuf[rd][b][3],
                    c2, s2, tx2, ty2);
        out[b * 3 + 0] = atan2f(s2, c2);
        out[b * 3 + 1] = tx2;
        out[b * 3 + 2] = ty2;
    }
}

// ---------------------------------------------------------------------------
extern "C" void kernel_launch(void* const* d_in, const int* in_sizes, int n_in,
                              void* d_out, int out_size) {
    const float* source = (const float*)d_in[0];   // (32, 2048, 2)
    const float* target = (const float*)d_in[1];   // (32, 2048, 2)
    const float* init_t = (const float*)d_in[2];   // (32, 3)
    float* out = (float*)d_out;                    // (32, 3)

    for (int it = 0; it < ITERS; ++it)
        icp_iter_kernel<<<BB * CHUNKS, TPB>>>(source, target, init_t, it);
    icp_final_kernel<<<BB, 32>>>(out);
}